// round 2
// baseline (speedup 1.0000x reference)
#include <cuda_runtime.h>

#define NSEG 2048
#define EPS 1e-6f
#define THREADS 256

// Segment boundaries (batch is sorted).
__device__ int g_seg_start[NSEG + 1];

// Binary-search lower bound for each segment id.
__global__ void bounds_kernel(const int* __restrict__ batch, int n) {
    int g = blockIdx.x * blockDim.x + threadIdx.x;
    if (g > NSEG) return;
    int lo = 0, hi = n;
    while (lo < hi) {
        int mid = (lo + hi) >> 1;
        if (batch[mid] < g) lo = mid + 1; else hi = mid;
    }
    g_seg_start[g] = lo;
}

__device__ __forceinline__ float warp_sum(float x) {
#pragma unroll
    for (int o = 16; o > 0; o >>= 1) x += __shfl_xor_sync(0xFFFFFFFFu, x, o);
    return x;
}

// One CTA per segment: pass 1 accumulates stats, pass 2 re-reads (L2-hit) and writes.
__global__ void fused_seg_kernel(const float4* __restrict__ s4,
                                 const float4* __restrict__ v4,
                                 const float4* __restrict__ w4,
                                 const float4* __restrict__ b4,
                                 float4* __restrict__ outs4,
                                 float4* __restrict__ outv4) {
    extern __shared__ char l2_throttle_pad[];  // unused; caps occupancy to 3 CTA/SM
    (void)l2_throttle_pad;
    __shared__ float red[3][8];
    __shared__ float stats[3];  // m, invvar, invvm

    int seg = blockIdx.x;
    int start = g_seg_start[seg];
    int count = g_seg_start[seg + 1] - start;
    if (count == 0) return;

    int t = threadIdx.x;
    int warp = t >> 5, lane = t & 31;
    long long sbase = (long long)start * 64;   // float4 index into s
    long long vbase = (long long)start * 96;   // float4 index into v
    int ns4 = count * 64;
    int nv4 = count * 96;

    // ---- Pass 1: accumulate sums (fills L2 with this segment's data) ----
    float ss = 0.0f, ss2 = 0.0f, sv2 = 0.0f;
#pragma unroll 4
    for (int i = t; i < ns4; i += THREADS) {
        float4 a = s4[sbase + i];
        ss  += a.x + a.y + a.z + a.w;
        ss2 += a.x * a.x + a.y * a.y + a.z * a.z + a.w * a.w;
    }
#pragma unroll 4
    for (int i = t; i < nv4; i += THREADS) {
        float4 a = v4[vbase + i];
        sv2 += a.x * a.x + a.y * a.y + a.z * a.z + a.w * a.w;
    }

    ss  = warp_sum(ss);
    ss2 = warp_sum(ss2);
    sv2 = warp_sum(sv2);
    if (lane == 0) { red[0][warp] = ss; red[1][warp] = ss2; red[2][warp] = sv2; }
    __syncthreads();
    if (warp == 0) {
        float a0 = (lane < 8) ? red[0][lane] : 0.0f;
        float a1 = (lane < 8) ? red[1][lane] : 0.0f;
        float a2 = (lane < 8) ? red[2][lane] : 0.0f;
        a0 = warp_sum(a0); a1 = warp_sum(a1); a2 = warp_sum(a2);
        if (lane == 0) {
            float cnt = (float)count;
            float denom_s = cnt * 256.0f;
            float m = a0 / denom_s;
            float var = a1 / denom_s - m * m;
            var = fmaxf(var, EPS);
            float vmean = a2 / (cnt * 128.0f);
            vmean = fmaxf(vmean, EPS);
            stats[0] = m;
            stats[1] = 1.0f / var;
            stats[2] = 1.0f / vmean;
        }
    }
    __syncthreads();

    float m   = stats[0];
    float ivr = stats[1];
    float ivm = stats[2];

    // ---- Pass 2: re-read (should hit L2), normalize, streaming-store ----
#pragma unroll 4
    for (int i = t; i < ns4; i += THREADS) {
        long long g = sbase + i;
        float4 a = __ldcs(&s4[g]);           // evict-first: done with it after this
        int cg = (int)(g & 63);              // channel group (64 float4 per node)
        float4 w = __ldg(&w4[cg]);
        float4 b = __ldg(&b4[cg]);
        float4 o;
        o.x = (a.x - m) * ivr * w.x + b.x;
        o.y = (a.y - m) * ivr * w.y + b.y;
        o.z = (a.z - m) * ivr * w.z + b.z;
        o.w = (a.w - m) * ivr * w.w + b.w;
        __stcs(&outs4[g], o);                // streaming store: don't pollute L2
    }
#pragma unroll 4
    for (int i = t; i < nv4; i += THREADS) {
        long long g = vbase + i;
        float4 a = __ldcs(&v4[g]);
        float4 o;
        o.x = a.x * ivm;
        o.y = a.y * ivm;
        o.z = a.z * ivm;
        o.w = a.w * ivm;
        __stcs(&outv4[g], o);
    }
}

extern "C" void kernel_launch(void* const* d_in, const int* in_sizes, int n_in,
                              void* d_out, int out_size) {
    const float* s      = (const float*)d_in[0];
    const float* v      = (const float*)d_in[1];
    const float* weight = (const float*)d_in[2];
    const float* bias   = (const float*)d_in[3];
    const int*   batch  = (const int*)d_in[4];

    int n = in_sizes[4];
    float* out_s = (float*)d_out;
    float* out_v = out_s + (size_t)n * 256;

    bounds_kernel<<<(NSEG + 1 + 255) / 256, 256>>>(batch, n);

    // 72KB dynamic smem -> 3 CTAs/SM -> ~444 resident CTAs * ~240KB segment data
    // fits the 126MB L2 so pass-2 re-reads hit L2.
    const int SMEM_THROTTLE = 72 * 1024;
    static bool attr_set = false;
    // Idempotent, non-stream host call (safe under capture); set every call is fine.
    cudaFuncSetAttribute(fused_seg_kernel,
                         cudaFuncAttributeMaxDynamicSharedMemorySize, SMEM_THROTTLE);
    (void)attr_set;

    fused_seg_kernel<<<NSEG, THREADS, SMEM_THROTTLE>>>(
        (const float4*)s, (const float4*)v,
        (const float4*)weight, (const float4*)bias,
        (float4*)out_s, (float4*)out_v);
}

// round 3
// speedup vs baseline: 1.2232x; 1.2232x over previous
#include <cuda_runtime.h>

#define NSEG 2048
#define EPS 1e-6f
#define THREADS 512
#define NWARPS (THREADS / 32)

// Segment boundaries (batch is sorted).
__device__ int g_seg_start[NSEG + 1];

__global__ void bounds_kernel(const int* __restrict__ batch, int n) {
    int g = blockIdx.x * blockDim.x + threadIdx.x;
    if (g > NSEG) return;
    int lo = 0, hi = n;
    while (lo < hi) {
        int mid = (lo + hi) >> 1;
        if (batch[mid] < g) lo = mid + 1; else hi = mid;
    }
    g_seg_start[g] = lo;
}

__device__ __forceinline__ float warp_sum(float x) {
#pragma unroll
    for (int o = 16; o > 0; o >>= 1) x += __shfl_xor_sync(0xFFFFFFFFu, x, o);
    return x;
}

// One CTA per segment: pass 1 accumulates stats (fills L2), pass 2 re-reads
// (L2 hit) and writes with streaming stores. 512 threads for MLP; dummy
// dynamic smem throttles to 3 CTAs/SM so the resident working set
// (444 CTAs x ~240KB) stays inside the 126MB L2.
__global__ void __launch_bounds__(THREADS, 3)
fused_seg_kernel(const float4* __restrict__ s4,
                 const float4* __restrict__ v4,
                 const float4* __restrict__ w4,
                 const float4* __restrict__ b4,
                 float4* __restrict__ outs4,
                 float4* __restrict__ outv4) {
    extern __shared__ char l2_throttle_pad[];  // occupancy throttle only
    (void)l2_throttle_pad;
    __shared__ float red[3][NWARPS];
    __shared__ float stats[3];  // m, invvar, invvm

    int seg = blockIdx.x;
    int start = g_seg_start[seg];
    int count = g_seg_start[seg + 1] - start;
    if (count == 0) return;

    int t = threadIdx.x;
    int warp = t >> 5, lane = t & 31;
    long long sbase = (long long)start * 64;   // float4 index into s
    long long vbase = (long long)start * 96;   // float4 index into v
    int ns4 = count * 64;
    int nv4 = count * 96;

    // ---- Pass 1: accumulate sums ----
    float ss = 0.0f, ss2 = 0.0f, sv2 = 0.0f;
#pragma unroll 4
    for (int i = t; i < ns4; i += THREADS) {
        float4 a = s4[sbase + i];
        ss  += a.x + a.y + a.z + a.w;
        ss2 += a.x * a.x + a.y * a.y + a.z * a.z + a.w * a.w;
    }
#pragma unroll 4
    for (int i = t; i < nv4; i += THREADS) {
        float4 a = v4[vbase + i];
        sv2 += a.x * a.x + a.y * a.y + a.z * a.z + a.w * a.w;
    }

    ss  = warp_sum(ss);
    ss2 = warp_sum(ss2);
    sv2 = warp_sum(sv2);
    if (lane == 0) { red[0][warp] = ss; red[1][warp] = ss2; red[2][warp] = sv2; }
    __syncthreads();
    if (warp == 0) {
        float a0 = (lane < NWARPS) ? red[0][lane] : 0.0f;
        float a1 = (lane < NWARPS) ? red[1][lane] : 0.0f;
        float a2 = (lane < NWARPS) ? red[2][lane] : 0.0f;
        a0 = warp_sum(a0); a1 = warp_sum(a1); a2 = warp_sum(a2);
        if (lane == 0) {
            float cnt = (float)count;
            float denom_s = cnt * 256.0f;
            float m = a0 / denom_s;
            float var = a1 / denom_s - m * m;
            var = fmaxf(var, EPS);
            float vmean = a2 / (cnt * 128.0f);
            vmean = fmaxf(vmean, EPS);
            stats[0] = m;
            stats[1] = 1.0f / var;
            stats[2] = 1.0f / vmean;
        }
    }
    __syncthreads();

    float m   = stats[0];
    float ivr = stats[1];
    float ivm = stats[2];

    // ---- Pass 2: re-read (L2 hit), normalize, streaming-store ----
#pragma unroll 4
    for (int i = t; i < ns4; i += THREADS) {
        long long g = sbase + i;
        float4 a = __ldcs(&s4[g]);           // evict-first after consumption
        int cg = (int)(g & 63);              // 64 float4 per node row
        float4 w = __ldg(&w4[cg]);
        float4 b = __ldg(&b4[cg]);
        float4 o;
        o.x = (a.x - m) * ivr * w.x + b.x;
        o.y = (a.y - m) * ivr * w.y + b.y;
        o.z = (a.z - m) * ivr * w.z + b.z;
        o.w = (a.w - m) * ivr * w.w + b.w;
        __stcs(&outs4[g], o);                // don't pollute L2 with outputs
    }
#pragma unroll 4
    for (int i = t; i < nv4; i += THREADS) {
        long long g = vbase + i;
        float4 a = __ldcs(&v4[g]);
        float4 o;
        o.x = a.x * ivm;
        o.y = a.y * ivm;
        o.z = a.z * ivm;
        o.w = a.w * ivm;
        __stcs(&outv4[g], o);
    }
}

extern "C" void kernel_launch(void* const* d_in, const int* in_sizes, int n_in,
                              void* d_out, int out_size) {
    const float* s      = (const float*)d_in[0];
    const float* v      = (const float*)d_in[1];
    const float* weight = (const float*)d_in[2];
    const float* bias   = (const float*)d_in[3];
    const int*   batch  = (const int*)d_in[4];

    int n = in_sizes[4];
    float* out_s = (float*)d_out;
    float* out_v = out_s + (size_t)n * 256;

    bounds_kernel<<<(NSEG + 1 + 255) / 256, 256>>>(batch, n);

    // 64KB dynamic smem -> 3 CTAs/SM (228KB smem/SM), 512 thr -> 48 warps/SM.
    const int SMEM_THROTTLE = 64 * 1024;
    cudaFuncSetAttribute(fused_seg_kernel,
                         cudaFuncAttributeMaxDynamicSharedMemorySize, SMEM_THROTTLE);

    fused_seg_kernel<<<NSEG, THREADS, SMEM_THROTTLE>>>(
        (const float4*)s, (const float4*)v,
        (const float4*)weight, (const float4*)bias,
        (float4*)out_s, (float4*)out_v);
}

// round 4
// speedup vs baseline: 1.3489x; 1.1028x over previous
#include <cuda_runtime.h>

#define NSEG 2048
#define EPS 1e-6f
#define THREADS 512
#define NWARPS (THREADS / 32)
#define SMEM_F4 4096   // 64KB of float4 stash for the s-stream head

__device__ __forceinline__ float warp_sum(float x) {
#pragma unroll
    for (int o = 16; o > 0; o >>= 1) x += __shfl_xor_sync(0xFFFFFFFFu, x, o);
    return x;
}

__device__ __forceinline__ int lower_bound(const int* __restrict__ batch, int n, int key) {
    int lo = 0, hi = n;
    while (lo < hi) {
        int mid = (lo + hi) >> 1;
        if (__ldg(&batch[mid]) < key) lo = mid + 1; else hi = mid;
    }
    return lo;
}

// One CTA per segment. Pass 1: accumulate stats, stashing the head of the
// s-stream in 64KB smem (doubles as the 3-CTA/SM occupancy throttle so the
// resident working set stays inside L2). Pass 2 in LIFO order (v first, then
// s), re-reading from smem/L2, streaming stores.
__global__ void __launch_bounds__(THREADS, 3)
fused_seg_kernel(const float4* __restrict__ s4,
                 const float4* __restrict__ v4,
                 const float4* __restrict__ w4,
                 const float4* __restrict__ b4,
                 const int*    __restrict__ batch,
                 int n,
                 float4* __restrict__ outs4,
                 float4* __restrict__ outv4) {
    extern __shared__ float4 s_stash[];      // SMEM_F4 entries
    __shared__ float red[3][NWARPS];
    __shared__ float stats[3];               // m, invvar, invvm
    __shared__ int bounds[2];

    int seg = blockIdx.x;
    int t = threadIdx.x;
    int warp = t >> 5, lane = t & 31;

    // Per-CTA segment bounds: two parallel binary searches (batch is sorted;
    // the 800KB batch array is L2-resident after the first wave).
    if (warp == 0 && lane < 2)
        bounds[lane] = lower_bound(batch, n, seg + lane);
    __syncthreads();

    int start = bounds[0];
    int count = bounds[1] - start;
    if (count == 0) return;

    long long sbase = (long long)start * 64;   // float4 index into s
    long long vbase = (long long)start * 96;   // float4 index into v
    int ns4 = count * 64;
    int nv4 = count * 96;
    int stash_n = (ns4 < SMEM_F4) ? ns4 : SMEM_F4;

    // ---- Pass 1: accumulate sums; stash s-head into smem ----
    float ss = 0.0f, ss2 = 0.0f, sv2 = 0.0f;
#pragma unroll 2
    for (int i = t; i < ns4; i += THREADS) {
        float4 a = s4[sbase + i];
        if (i < SMEM_F4) s_stash[i] = a;
        ss  += a.x + a.y + a.z + a.w;
        ss2 += a.x * a.x + a.y * a.y + a.z * a.z + a.w * a.w;
    }
#pragma unroll 4
    for (int i = t; i < nv4; i += THREADS) {
        float4 a = v4[vbase + i];
        sv2 += a.x * a.x + a.y * a.y + a.z * a.z + a.w * a.w;
    }

    ss  = warp_sum(ss);
    ss2 = warp_sum(ss2);
    sv2 = warp_sum(sv2);
    if (lane == 0) { red[0][warp] = ss; red[1][warp] = ss2; red[2][warp] = sv2; }
    __syncthreads();
    if (warp == 0) {
        float a0 = (lane < NWARPS) ? red[0][lane] : 0.0f;
        float a1 = (lane < NWARPS) ? red[1][lane] : 0.0f;
        float a2 = (lane < NWARPS) ? red[2][lane] : 0.0f;
        a0 = warp_sum(a0); a1 = warp_sum(a1); a2 = warp_sum(a2);
        if (lane == 0) {
            float cnt = (float)count;
            float denom_s = cnt * 256.0f;
            float m = a0 / denom_s;
            float var = a1 / denom_s - m * m;
            var = fmaxf(var, EPS);
            float vmean = a2 / (cnt * 128.0f);
            vmean = fmaxf(vmean, EPS);
            stats[0] = m;
            stats[1] = 1.0f / var;
            stats[2] = 1.0f / vmean;
        }
    }
    __syncthreads();

    float m   = stats[0];
    float ivr = stats[1];
    float ivm = stats[2];

    // ---- Pass 2 (LIFO): v first (youngest in L2), then s ----
#pragma unroll 4
    for (int i = t; i < nv4; i += THREADS) {
        long long g = vbase + i;
        float4 a = __ldcs(&v4[g]);
        float4 o;
        o.x = a.x * ivm;
        o.y = a.y * ivm;
        o.z = a.z * ivm;
        o.w = a.w * ivm;
        __stcs(&outv4[g], o);
    }
#pragma unroll 2
    for (int i = t; i < ns4; i += THREADS) {
        long long g = sbase + i;
        float4 a = (i < stash_n) ? s_stash[i] : __ldcs(&s4[g]);
        int cg = (int)(g & 63);              // 64 float4 per node row
        float4 w = __ldg(&w4[cg]);
        float4 b = __ldg(&b4[cg]);
        float4 o;
        o.x = (a.x - m) * ivr * w.x + b.x;
        o.y = (a.y - m) * ivr * w.y + b.y;
        o.z = (a.z - m) * ivr * w.z + b.z;
        o.w = (a.w - m) * ivr * w.w + b.w;
        __stcs(&outs4[g], o);
    }
}

extern "C" void kernel_launch(void* const* d_in, const int* in_sizes, int n_in,
                              void* d_out, int out_size) {
    const float* s      = (const float*)d_in[0];
    const float* v      = (const float*)d_in[1];
    const float* weight = (const float*)d_in[2];
    const float* bias   = (const float*)d_in[3];
    const int*   batch  = (const int*)d_in[4];

    int n = in_sizes[4];
    float* out_s = (float*)d_out;
    float* out_v = out_s + (size_t)n * 256;

    const int SMEM_BYTES = SMEM_F4 * 16;   // 64KB -> 3 CTAs/SM throttle + stash
    cudaFuncSetAttribute(fused_seg_kernel,
                         cudaFuncAttributeMaxDynamicSharedMemorySize, SMEM_BYTES);

    fused_seg_kernel<<<NSEG, THREADS, SMEM_BYTES>>>(
        (const float4*)s, (const float4*)v,
        (const float4*)weight, (const float4*)bias,
        batch, n,
        (float4*)out_s, (float4*)out_v);
}

// round 5
// speedup vs baseline: 1.4521x; 1.0765x over previous
#include <cuda_runtime.h>

#define NSEG 2048
#define EPS 1e-6f
#define THREADS 1024
#define NWARPS (THREADS / 32)
#define SMEM_F4 6144   // 96KB float4 stash: covers ~98% of a segment's s-data

__device__ __forceinline__ float warp_sum(float x) {
#pragma unroll
    for (int o = 16; o > 0; o >>= 1) x += __shfl_xor_sync(0xFFFFFFFFu, x, o);
    return x;
}

__device__ __forceinline__ int lower_bound(const int* __restrict__ batch, int n, int key) {
    int lo = 0, hi = n;
    while (lo < hi) {
        int mid = (lo + hi) >> 1;
        if (__ldg(&batch[mid]) < key) lo = mid + 1; else hi = mid;
    }
    return lo;
}

// One CTA per segment, 1024 threads, 2 CTAs/SM (full 2048 thr/SM for MLP).
// Pass 1: accumulate stats; stash the s-stream in 96KB smem (nearly all of
// it) so pass 2's s-read never touches L2/DRAM. v is re-read from L2
// (304 resident CTAs x ~146KB = ~44MB << 126MB L2). Streaming stores.
__global__ void __launch_bounds__(THREADS, 2)
fused_seg_kernel(const float4* __restrict__ s4,
                 const float4* __restrict__ v4,
                 const float4* __restrict__ w4,
                 const float4* __restrict__ b4,
                 const int*    __restrict__ batch,
                 int n,
                 float4* __restrict__ outs4,
                 float4* __restrict__ outv4) {
    extern __shared__ float4 s_stash[];      // SMEM_F4 entries
    __shared__ float red[3][NWARPS];
    __shared__ float stats[3];               // m, invvar, invvm
    __shared__ int bounds[2];

    int seg = blockIdx.x;
    int t = threadIdx.x;
    int warp = t >> 5, lane = t & 31;

    if (warp == 0 && lane < 2)
        bounds[lane] = lower_bound(batch, n, seg + lane);
    __syncthreads();

    int start = bounds[0];
    int count = bounds[1] - start;
    if (count == 0) return;

    long long sbase = (long long)start * 64;   // float4 index into s
    long long vbase = (long long)start * 96;   // float4 index into v
    int ns4 = count * 64;
    int nv4 = count * 96;
    int stash_n = (ns4 < SMEM_F4) ? ns4 : SMEM_F4;

    // ---- Pass 1: accumulate sums; stash s into smem ----
    float ss = 0.0f, ss2 = 0.0f, sv2 = 0.0f;
#pragma unroll 2
    for (int i = t; i < ns4; i += THREADS) {
        float4 a = s4[sbase + i];
        if (i < SMEM_F4) s_stash[i] = a;
        ss  += a.x + a.y + a.z + a.w;
        ss2 += a.x * a.x + a.y * a.y + a.z * a.z + a.w * a.w;
    }
#pragma unroll 2
    for (int i = t; i < nv4; i += THREADS) {
        float4 a = v4[vbase + i];
        sv2 += a.x * a.x + a.y * a.y + a.z * a.z + a.w * a.w;
    }

    ss  = warp_sum(ss);
    ss2 = warp_sum(ss2);
    sv2 = warp_sum(sv2);
    if (lane == 0) { red[0][warp] = ss; red[1][warp] = ss2; red[2][warp] = sv2; }
    __syncthreads();
    if (warp == 0) {
        float a0 = (lane < NWARPS) ? red[0][lane] : 0.0f;
        float a1 = (lane < NWARPS) ? red[1][lane] : 0.0f;
        float a2 = (lane < NWARPS) ? red[2][lane] : 0.0f;
        a0 = warp_sum(a0); a1 = warp_sum(a1); a2 = warp_sum(a2);
        if (lane == 0) {
            float cnt = (float)count;
            float denom_s = cnt * 256.0f;
            float m = a0 / denom_s;
            float var = a1 / denom_s - m * m;
            var = fmaxf(var, EPS);
            float vmean = a2 / (cnt * 128.0f);
            vmean = fmaxf(vmean, EPS);
            stats[0] = m;
            stats[1] = 1.0f / var;
            stats[2] = 1.0f / vmean;
        }
    }
    __syncthreads();

    float m   = stats[0];
    float ivr = stats[1];
    float ivm = stats[2];

    // ---- Pass 2 (LIFO): v first (from L2), then s (from smem) ----
#pragma unroll 2
    for (int i = t; i < nv4; i += THREADS) {
        long long g = vbase + i;
        float4 a = __ldcs(&v4[g]);
        float4 o;
        o.x = a.x * ivm;
        o.y = a.y * ivm;
        o.z = a.z * ivm;
        o.w = a.w * ivm;
        __stcs(&outv4[g], o);
    }
#pragma unroll 2
    for (int i = t; i < ns4; i += THREADS) {
        long long g = sbase + i;
        float4 a = (i < stash_n) ? s_stash[i] : __ldcs(&s4[g]);
        int cg = (int)(g & 63);              // 64 float4 per node row
        float4 w = __ldg(&w4[cg]);
        float4 b = __ldg(&b4[cg]);
        float4 o;
        o.x = (a.x - m) * ivr * w.x + b.x;
        o.y = (a.y - m) * ivr * w.y + b.y;
        o.z = (a.z - m) * ivr * w.z + b.z;
        o.w = (a.w - m) * ivr * w.w + b.w;
        __stcs(&outs4[g], o);
    }
}

extern "C" void kernel_launch(void* const* d_in, const int* in_sizes, int n_in,
                              void* d_out, int out_size) {
    const float* s      = (const float*)d_in[0];
    const float* v      = (const float*)d_in[1];
    const float* weight = (const float*)d_in[2];
    const float* bias   = (const float*)d_in[3];
    const int*   batch  = (const int*)d_in[4];

    int n = in_sizes[4];
    float* out_s = (float*)d_out;
    float* out_v = out_s + (size_t)n * 256;

    const int SMEM_BYTES = SMEM_F4 * 16;   // 96KB -> 2 CTAs/SM + s stash
    cudaFuncSetAttribute(fused_seg_kernel,
                         cudaFuncAttributeMaxDynamicSharedMemorySize, SMEM_BYTES);

    fused_seg_kernel<<<NSEG, THREADS, SMEM_BYTES>>>(
        (const float4*)s, (const float4*)v,
        (const float4*)weight, (const float4*)bias,
        batch, n,
        (float4*)out_s, (float4*)out_v);
}